// round 3
// baseline (speedup 1.0000x reference)
#include <cuda_runtime.h>
#include <cstdint>

// IOVPreTrainedEmbeddings: out[b,s,:] = (oov_map[x[b,s]] >= 0)
//                                         ? oov_embed[oov_map[x[b,s]], :]
//                                         : w2v[x[b,s], :]
//
// Shapes: x [128,1024], w2v [100000,300] f32, oov_embed [5000,300] f32,
//         oov_map [100000], out [128,1024,300] f32.
// NOTE: JAX without x64 downcasts int64 -> int32, so x and oov_map arrive
// as int32 buffers (previous round's rel_err=1.29 came from striding them
// as 8-byte ints).
//
// Pure HBM-bound gather: ~157MB read + ~157MB write. One float4 of output
// per thread (coalesced stores), source row selected per token.

static constexpr int TOKENS = 128 * 1024;   // B*S
static constexpr int DIM    = 300;
static constexpr int VEC    = DIM / 4;      // 75 float4 per row (1200B stride, 16B-aligned)
static constexpr long long TOTAL4 = (long long)TOKENS * VEC;  // 9,830,400

__global__ __launch_bounds__(256)
void iov_gather_kernel(const int*    __restrict__ x,
                       const float4* __restrict__ w2v,       // row stride VEC
                       const float4* __restrict__ oov_embed, // row stride VEC
                       const int*    __restrict__ oov_map,
                       float4*       __restrict__ out)
{
    int i = blockIdx.x * blockDim.x + threadIdx.x;
    if (i >= (int)TOTAL4) return;

    int token = i / VEC;          // mul-shift division by 75
    int chunk = i - token * VEC;

    // Per-token index loads: broadcast across the 75 threads of this token,
    // L1/L2 resident (x = 512KB, oov_map = 400KB).
    int id  = __ldg(&x[token]);
    int row = __ldg(&oov_map[id]);

    const float4* src = (row >= 0) ? (oov_embed + (long long)row * VEC)
                                   : (w2v       + (long long)id  * VEC);

    out[i] = __ldg(&src[chunk]);
}

extern "C" void kernel_launch(void* const* d_in, const int* in_sizes, int n_in,
                              void* d_out, int out_size)
{
    const int*    x         = (const int*)   d_in[0];
    const float4* w2v       = (const float4*)d_in[1];
    const float4* oov_embed = (const float4*)d_in[2];
    const int*    oov_map   = (const int*)   d_in[3];
    float4*       out       = (float4*)d_out;

    const int threads = 256;
    const int blocks  = (int)((TOTAL4 + threads - 1) / threads);
    iov_gather_kernel<<<blocks, threads>>>(x, w2v, oov_embed, oov_map, out);
}

// round 4
// speedup vs baseline: 1.3488x; 1.3488x over previous
#include <cuda_runtime.h>
#include <cstdint>

// IOVPreTrainedEmbeddings: out[b,s,:] = (oov_map[x[b,s]] >= 0)
//                                         ? oov_embed[oov_map[x[b,s]], :]
//                                         : w2v[x[b,s], :]
//
// x [128,1024] i32 (JAX x64-off downcast), w2v [100000,300] f32,
// oov_embed [5000,300] f32, oov_map [100000] i32, out [128,1024,300] f32.
//
// R3: ILP=4 unrolled gather. R2 measured DRAM=49.6% with issue=12.9% —
// classic MLP=1 dependent-chain limit (id -> map -> payload serial per
// thread). Front-batch 4 independent chains per thread to quadruple
// memory-level parallelism at every stage; coalescing is preserved by
// striding the 4 groups by the full grid width.

static constexpr int TOKENS = 128 * 1024;     // B*S
static constexpr int DIM    = 300;
static constexpr int VEC    = DIM / 4;        // 75 float4 per row (1200B stride)
static constexpr long long TOTAL4 = (long long)TOKENS * VEC;  // 9,830,400

static constexpr int THREADS = 256;
static constexpr int UNROLL  = 4;
static constexpr int BLOCKS  = (int)(TOTAL4 / ((long long)THREADS * UNROLL)); // 9600, exact
static constexpr int STRIDE  = THREADS * BLOCKS;  // 2,457,600

__global__ __launch_bounds__(THREADS)
void iov_gather_ilp4_kernel(const int*    __restrict__ x,
                            const float4* __restrict__ w2v,       // row stride VEC
                            const float4* __restrict__ oov_embed, // row stride VEC
                            const int*    __restrict__ oov_map,
                            float4*       __restrict__ out)
{
    const int base = blockIdx.x * THREADS + threadIdx.x;

    int idx[UNROLL];
    int id[UNROLL];
    int row[UNROLL];
    const float4* src[UNROLL];
    float4 val[UNROLL];

    // Phase 1: token ids (L1/L2-resident, broadcast across the 75 threads
    // of each token) — 4 independent loads in flight.
    #pragma unroll
    for (int k = 0; k < UNROLL; k++) {
        idx[k] = base + k * STRIDE;
        int token = idx[k] / VEC;             // mul-shift div by 75
        id[k] = __ldg(&x[token]);
    }

    // Phase 2: oov_map gathers — 4 in flight.
    #pragma unroll
    for (int k = 0; k < UNROLL; k++)
        row[k] = __ldg(&oov_map[id[k]]);

    // Phase 3: payload gathers (DRAM-bound) — 4 in flight.
    #pragma unroll
    for (int k = 0; k < UNROLL; k++) {
        int token = idx[k] / VEC;
        int chunk = idx[k] - token * VEC;
        src[k] = (row[k] >= 0) ? (oov_embed + (long long)row[k] * VEC + chunk)
                               : (w2v       + (long long)id[k]  * VEC + chunk);
        val[k] = __ldg(src[k]);
    }

    // Phase 4: coalesced stores.
    #pragma unroll
    for (int k = 0; k < UNROLL; k++)
        out[idx[k]] = val[k];
}

extern "C" void kernel_launch(void* const* d_in, const int* in_sizes, int n_in,
                              void* d_out, int out_size)
{
    const int*    x         = (const int*)   d_in[0];
    const float4* w2v       = (const float4*)d_in[1];
    const float4* oov_embed = (const float4*)d_in[2];
    const int*    oov_map   = (const int*)   d_in[3];
    float4*       out       = (float4*)d_out;

    iov_gather_ilp4_kernel<<<BLOCKS, THREADS>>>(x, w2v, oov_embed, oov_map, out);
}